// round 9
// baseline (speedup 1.0000x reference)
#include <cuda_runtime.h>
#include <cuda_bf16.h>
#include <cstddef>

// Problem constants
#define B_    8
#define H_    32
#define D_    128
#define DM_   4096
#define TC_   8192
#define TK_   8193
#define HD_   4096          // H*D
#define COLS3 12288         // 3*HD
#define SPLITK_QKV 32
#define KCH_QKV    128      // DM/SPLITK_QKV
#define SPLITK_OUT 32
#define KCH_OUT    128      // HD/SPLITK_OUT
#define CH    512           // keys per attention chunk
#define NCH   16            // TC/CH
#define NBH   256           // B*H
#define TPW   64            // tokens per warp (CH/8)
#define SCALE 0.08838834764831845f   // 1/sqrt(128)

#define OUT_SZ   (B_*DM_)                           // 32768
#define KCAT_SZ  ((size_t)NBH*TK_*D_)               // 268468224
#define KOFF     ((size_t)OUT_SZ)
#define VOFF     ((size_t)OUT_SZ + KCAT_SZ)

// ---------------- scratch (device globals; no allocation) ----------------
__device__ float g_qkv_part[SPLITK_QKV * B_ * COLS3];  // 12.6 MB
__device__ float g_qkv[B_ * COLS3];
__device__ float g_pm[NBH * NCH];
__device__ float g_pl[NBH * NCH];
__device__ float g_pacc[(size_t)NBH * NCH * D_];       // 2 MB
__device__ float g_o[B_ * HD_];
__device__ float g_o_part[SPLITK_OUT * B_ * HD_];      // 4 MB

// ---------------- kernel 1: QKV projection, split-K x32 (R5 exact) ----------------
__global__ void qkv_gemm(const float* __restrict__ x,
                         const float* __restrict__ Wq,
                         const float* __restrict__ Wk,
                         const float* __restrict__ Wv) {
    __shared__ float xs[KCH_QKV * 8];   // xs[kk*8 + r]
    const int split = blockIdx.y;
    const int col   = blockIdx.x * 256 + threadIdx.x;
    const int k0    = split * KCH_QKV;

    for (int idx = threadIdx.x; idx < KCH_QKV * 8; idx += 256) {
        int kk = idx >> 3, r = idx & 7;
        xs[idx] = x[r * DM_ + k0 + kk];
    }
    __syncthreads();

    const int mat  = col >> 12;           // 0:q 1:k 2:v
    const int lcol = col & 4095;
    const float* W = (mat == 0) ? Wq : ((mat == 1) ? Wk : Wv);
    const float* wp = W + (size_t)k0 * HD_ + lcol;

    float acc[8];
    #pragma unroll
    for (int r = 0; r < 8; r++) acc[r] = 0.f;

    for (int kk = 0; kk < KCH_QKV; kk += 8) {
        float w[8];
        #pragma unroll
        for (int j = 0; j < 8; j++) w[j] = wp[(size_t)(kk + j) * HD_];
        #pragma unroll
        for (int j = 0; j < 8; j++) {
            #pragma unroll
            for (int r = 0; r < 8; r++) acc[r] += xs[(kk + j) * 8 + r] * w[j];
        }
    }
    float* op = g_qkv_part + (size_t)split * (B_ * COLS3) + col;
    #pragma unroll
    for (int r = 0; r < 8; r++) op[(size_t)r * COLS3] = acc[r];
}

// ---------------- kernel 2 ----------------
__global__ void reduce_qkv() {
    int i = blockIdx.x * 256 + threadIdx.x;   // < 98304
    float s = 0.f;
    #pragma unroll
    for (int sp = 0; sp < SPLITK_QKV; sp++) s += g_qkv_part[(size_t)sp * (B_*COLS3) + i];
    g_qkv[i] = s;
}

// ---------------- kernel 3: append new-token k/v rows (also pads launch order
// so attn_chunk is the profiled 4th launch) ----------------
__global__ void new_kv(float* __restrict__ out) {
    int i = blockIdx.x * 256 + threadIdx.x;   // < NBH*D_ = 32768
    int bh = i >> 7;
    int d  = i & 127;
    int b  = bh >> 5;
    int h  = bh & 31;
    out[KOFF + ((size_t)bh * TK_ + TC_) * D_ + d] = g_qkv[b * COLS3 + HD_   + h * D_ + d];
    out[VOFF + ((size_t)bh * TK_ + TC_) * D_ + d] = g_qkv[b * COLS3 + 2*HD_ + h * D_ + d];
}

// ---------------- kernel 4: fused cache-copy + flash attention, warp-independent ----------------
// grid (NCH, NBH), block 256. Each warp owns 64 tokens end-to-end: K dot+copy,
// warp-local softmax stats, V weighted-accumulate+copy. One block barrier total.
__global__ void attn_chunk(const float* __restrict__ kc,
                           const float* __restrict__ vc,
                           float* __restrict__ out) {
    __shared__ float s_q[D_];
    __shared__ float s_sc[CH];          // warp-private slices
    __shared__ float s_m[8];
    __shared__ float s_l[8];
    __shared__ float s_vacc[8 * D_];

    const int bh  = blockIdx.y;
    const int c   = blockIdx.x;
    const int tid = threadIdx.x;
    const int b   = bh >> 5;
    const int h   = bh & 31;

    if (tid < D_) s_q[tid] = g_qkv[b * COLS3 + h * D_ + tid];
    __syncthreads();

    const int t0   = c * CH;
    const int w    = tid >> 5;
    const int lane = tid & 31;
    const int dd   = lane * 4;

    const float qx = s_q[dd], qy = s_q[dd+1], qz = s_q[dd+2], qw = s_q[dd+3];

    // ---- K pass: dot + copy (warp's own 64 rows) ----
    const float* kbase  = kc  + ((size_t)bh * TC_ + t0) * D_;
    float*       okbase = out + KOFF + ((size_t)bh * TK_ + t0) * D_;
    for (int i = 0; i < TPW; i++) {
        int t = w * TPW + i;
        float4 k4 = *(const float4*)(kbase + (size_t)t * D_ + dd);
        *(float4*)(okbase + (size_t)t * D_ + dd) = k4;
        float d = k4.x*qx + k4.y*qy + k4.z*qz + k4.w*qw;
        d += __shfl_down_sync(0xffffffffu, d, 16);
        d += __shfl_down_sync(0xffffffffu, d, 8);
        d += __shfl_down_sync(0xffffffffu, d, 4);
        d += __shfl_down_sync(0xffffffffu, d, 2);
        d += __shfl_down_sync(0xffffffffu, d, 1);
        if (lane == 0) s_sc[t] = d * SCALE;
    }
    __syncwarp();

    // ---- warp-local max (every lane computes redundantly; smem broadcast) ----
    float m_w = -3.4e38f;
    #pragma unroll 8
    for (int i = 0; i < TPW; i++) m_w = fmaxf(m_w, s_sc[w * TPW + i]);

    // ---- V pass: weighted accumulate + copy (warp's own 64 rows) ----
    const float* vbase  = vc  + ((size_t)bh * TC_ + t0) * D_;
    float*       ovbase = out + VOFF + ((size_t)bh * TK_ + t0) * D_;
    float ax = 0.f, ay = 0.f, az = 0.f, aw = 0.f, l_w = 0.f;
    for (int i = 0; i < TPW; i++) {
        int t = w * TPW + i;
        float4 v4 = *(const float4*)(vbase + (size_t)t * D_ + dd);
        *(float4*)(ovbase + (size_t)t * D_ + dd) = v4;
        float p = __expf(s_sc[t] - m_w);
        l_w += p;
        ax += p * v4.x; ay += p * v4.y; az += p * v4.z; aw += p * v4.w;
    }
    s_vacc[w * D_ + dd]     = ax;
    s_vacc[w * D_ + dd + 1] = ay;
    s_vacc[w * D_ + dd + 2] = az;
    s_vacc[w * D_ + dd + 3] = aw;
    if (lane == 0) { s_m[w] = m_w; s_l[w] = l_w; }
    __syncthreads();

    // ---- cross-warp merge with rescale (flash combine within the chunk) ----
    if (tid < D_) {
        float mb = s_m[0];
        #pragma unroll
        for (int g = 1; g < 8; g++) mb = fmaxf(mb, s_m[g]);
        float acc = 0.f, l = 0.f;
        #pragma unroll
        for (int g = 0; g < 8; g++) {
            float wg = __expf(s_m[g] - mb);
            acc += s_vacc[g * D_ + tid] * wg;
            l   += s_l[g] * wg;
        }
        g_pacc[((size_t)bh * NCH + c) * D_ + tid] = acc;
        if (tid == 0) { g_pm[bh * NCH + c] = mb; g_pl[bh * NCH + c] = l; }
    }
}

// ---------------- kernel 5: combine partials + new token ----------------
// grid 256, block 128. (R5 body minus the new-kv writes)
__global__ void combine() {
    __shared__ float s_red[D_];
    const int bh = blockIdx.x;
    const int d  = threadIdx.x;
    const int b  = bh >> 5;
    const int h  = bh & 31;

    const float q  = g_qkv[b * COLS3 +           h * D_ + d];
    const float kn = g_qkv[b * COLS3 + HD_  +    h * D_ + d];
    const float vn = g_qkv[b * COLS3 + 2*HD_ +   h * D_ + d];

    s_red[d] = q * kn;
    __syncthreads();
    for (int off = 64; off > 0; off >>= 1) {
        if (d < off) s_red[d] += s_red[d + off];
        __syncthreads();
    }
    const float snew = s_red[0] * SCALE;

    float M = snew;
    #pragma unroll
    for (int c = 0; c < NCH; c++) M = fmaxf(M, g_pm[bh * NCH + c]);

    float en = __expf(snew - M);
    float L  = en;
    float o  = en * vn;
    #pragma unroll
    for (int c = 0; c < NCH; c++) {
        float wgt = __expf(g_pm[bh * NCH + c] - M);
        L += g_pl[bh * NCH + c] * wgt;
        o += g_pacc[((size_t)bh * NCH + c) * D_ + d] * wgt;
    }
    g_o[b * HD_ + h * D_ + d] = o / L;
}

// ---------------- kernel 6: output projection o @ Wo, split-K x32 (R5 exact) ----------------
__global__ void out_gemm(const float* __restrict__ Wo) {
    __shared__ float xs[KCH_OUT * 8];
    const int split = blockIdx.y;
    const int col   = blockIdx.x * 256 + threadIdx.x;
    const int k0    = split * KCH_OUT;

    for (int idx = threadIdx.x; idx < KCH_OUT * 8; idx += 256) {
        int kk = idx >> 3, r = idx & 7;
        xs[idx] = g_o[r * HD_ + k0 + kk];
    }
    __syncthreads();

    const float* wp = Wo + (size_t)k0 * DM_ + col;
    float acc[8];
    #pragma unroll
    for (int r = 0; r < 8; r++) acc[r] = 0.f;

    for (int kk = 0; kk < KCH_OUT; kk += 8) {
        float w[8];
        #pragma unroll
        for (int j = 0; j < 8; j++) w[j] = wp[(size_t)(kk + j) * DM_];
        #pragma unroll
        for (int j = 0; j < 8; j++) {
            #pragma unroll
            for (int r = 0; r < 8; r++) acc[r] += xs[(kk + j) * 8 + r] * w[j];
        }
    }
    float* op = g_o_part + (size_t)split * (B_ * DM_) + col;
    #pragma unroll
    for (int r = 0; r < 8; r++) op[(size_t)r * DM_] = acc[r];
}

__global__ void reduce_out(float* __restrict__ out) {
    int i = blockIdx.x * 256 + threadIdx.x;   // < 32768
    float s = 0.f;
    #pragma unroll
    for (int sp = 0; sp < SPLITK_OUT; sp++) s += g_o_part[(size_t)sp * (B_*DM_) + i];
    out[i] = s;
}

// ---------------- launch ----------------
extern "C" void kernel_launch(void* const* d_in, const int* in_sizes, int n_in,
                              void* d_out, int out_size) {
    const float* x       = (const float*)d_in[0];
    const float* Wq      = (const float*)d_in[1];
    const float* Wk      = (const float*)d_in[2];
    const float* Wv      = (const float*)d_in[3];
    const float* Wo      = (const float*)d_in[4];
    const float* k_cache = (const float*)d_in[5];
    const float* v_cache = (const float*)d_in[6];
    float* out = (float*)d_out;

    qkv_gemm<<<dim3(48, SPLITK_QKV), 256>>>(x, Wq, Wk, Wv);   // 1
    reduce_qkv<<<(B_ * COLS3) / 256, 256>>>();                // 2
    new_kv<<<(NBH * D_) / 256, 256>>>(out);                   // 3
    attn_chunk<<<dim3(NCH, NBH), 256>>>(k_cache, v_cache, out); // 4 (profiled)
    combine<<<NBH, D_>>>();                                   // 5
    out_gemm<<<dim3(16, SPLITK_OUT), 256>>>(Wo);              // 6
    reduce_out<<<(B_ * DM_) / 256, 256>>>(out);               // 7
}

// round 10
// speedup vs baseline: 1.0073x; 1.0073x over previous
#include <cuda_runtime.h>
#include <cuda_bf16.h>
#include <cstddef>

// Problem constants
#define B_    8
#define H_    32
#define D_    128
#define DM_   4096
#define TC_   8192
#define TK_   8193
#define HD_   4096          // H*D
#define COLS3 12288         // 3*HD
#define SPLITK_QKV 32
#define KCH_QKV    128      // DM/SPLITK_QKV
#define SPLITK_OUT 32
#define KCH_OUT    128      // HD/SPLITK_OUT
#define CH    512           // keys per attention chunk
#define NCH   16            // TC/CH
#define NBH   256           // B*H
#define SCALE 0.08838834764831845f   // 1/sqrt(128)

#define OUT_SZ   (B_*DM_)                           // 32768
#define KCAT_SZ  ((size_t)NBH*TK_*D_)               // 268468224
#define KOFF     ((size_t)OUT_SZ)
#define VOFF     ((size_t)OUT_SZ + KCAT_SZ)

// ---------------- scratch (device globals; no allocation) ----------------
__device__ float g_qkv_part[SPLITK_QKV * B_ * COLS3];  // 12.6 MB
__device__ float g_qkv[B_ * COLS3];
__device__ float g_pm[NBH * NCH];
__device__ float g_pl[NBH * NCH];
__device__ float g_pacc[(size_t)NBH * NCH * D_];       // 2 MB
__device__ float g_o[B_ * HD_];
__device__ float g_o_part[SPLITK_OUT * B_ * HD_];      // 4 MB

// ---------------- kernel 1: QKV projection, split-K x32 (R5 exact) ----------------
// grid (48, 32), block 256.
__global__ void qkv_gemm(const float* __restrict__ x,
                         const float* __restrict__ Wq,
                         const float* __restrict__ Wk,
                         const float* __restrict__ Wv) {
    __shared__ float xs[KCH_QKV * 8];   // xs[kk*8 + r]
    const int split = blockIdx.y;
    const int col   = blockIdx.x * 256 + threadIdx.x;
    const int k0    = split * KCH_QKV;

    for (int idx = threadIdx.x; idx < KCH_QKV * 8; idx += 256) {
        int kk = idx >> 3, r = idx & 7;
        xs[idx] = x[r * DM_ + k0 + kk];
    }
    __syncthreads();

    const int mat  = col >> 12;           // 0:q 1:k 2:v
    const int lcol = col & 4095;
    const float* W = (mat == 0) ? Wq : ((mat == 1) ? Wk : Wv);
    const float* wp = W + (size_t)k0 * HD_ + lcol;

    float acc[8];
    #pragma unroll
    for (int r = 0; r < 8; r++) acc[r] = 0.f;

    for (int kk = 0; kk < KCH_QKV; kk += 8) {
        float w[8];
        #pragma unroll
        for (int j = 0; j < 8; j++) w[j] = wp[(size_t)(kk + j) * HD_];
        #pragma unroll
        for (int j = 0; j < 8; j++) {
            #pragma unroll
            for (int r = 0; r < 8; r++) acc[r] += xs[(kk + j) * 8 + r] * w[j];
        }
    }
    float* op = g_qkv_part + (size_t)split * (B_ * COLS3) + col;
    #pragma unroll
    for (int r = 0; r < 8; r++) op[(size_t)r * COLS3] = acc[r];
}

__global__ void reduce_qkv() {
    int i = blockIdx.x * 256 + threadIdx.x;   // < 98304
    float s = 0.f;
    #pragma unroll
    for (int sp = 0; sp < SPLITK_QKV; sp++) s += g_qkv_part[(size_t)sp * (B_*COLS3) + i];
    g_qkv[i] = s;
}

// ---------------- kernel 2: fused cache-copy + flash attention chunk ----------------
// grid (NCH, NBH), block 256. R5 exact body; ONLY change: __stcs on copy stores.
__global__ void attn_chunk(const float* __restrict__ kc,
                           const float* __restrict__ vc,
                           float* __restrict__ out) {
    __shared__ float s_q[D_];
    __shared__ float s_sc[CH];
    __shared__ float s_red[256];
    __shared__ float s_vacc[8 * D_];

    const int bh  = blockIdx.y;
    const int c   = blockIdx.x;
    const int tid = threadIdx.x;
    const int b   = bh >> 5;
    const int h   = bh & 31;

    if (tid < D_) s_q[tid] = g_qkv[b * COLS3 + h * D_ + tid];
    __syncthreads();

    const int t0   = c * CH;
    const int w    = tid >> 5;
    const int lane = tid & 31;
    const int dd   = lane * 4;

    const float qx = s_q[dd], qy = s_q[dd+1], qz = s_q[dd+2], qw = s_q[dd+3];

    // ---- K pass: dot + copy (streaming store) ----
    const float* kbase  = kc  + ((size_t)bh * TC_ + t0) * D_;
    float*       okbase = out + KOFF + ((size_t)bh * TK_ + t0) * D_;
    for (int i = 0; i < CH / 8; i++) {
        int t = w * (CH / 8) + i;
        float4 k4 = *(const float4*)(kbase + (size_t)t * D_ + dd);
        __stcs((float4*)(okbase + (size_t)t * D_ + dd), k4);
        float d = k4.x*qx + k4.y*qy + k4.z*qz + k4.w*qw;
        d += __shfl_down_sync(0xffffffffu, d, 16);
        d += __shfl_down_sync(0xffffffffu, d, 8);
        d += __shfl_down_sync(0xffffffffu, d, 4);
        d += __shfl_down_sync(0xffffffffu, d, 2);
        d += __shfl_down_sync(0xffffffffu, d, 1);
        if (lane == 0) s_sc[t] = d * SCALE;
    }
    __syncthreads();

    // ---- local max ----
    s_red[tid] = fmaxf(s_sc[tid], s_sc[tid + 256]);
    __syncthreads();
    for (int off = 128; off > 0; off >>= 1) {
        if (tid < off) s_red[tid] = fmaxf(s_red[tid], s_red[tid + off]);
        __syncthreads();
    }
    const float m = s_red[0];
    __syncthreads();

    // ---- exp + sum ----
    float e0 = __expf(s_sc[tid] - m);
    float e1 = __expf(s_sc[tid + 256] - m);
    s_sc[tid] = e0; s_sc[tid + 256] = e1;
    s_red[tid] = e0 + e1;
    __syncthreads();
    for (int off = 128; off > 0; off >>= 1) {
        if (tid < off) s_red[tid] += s_red[tid + off];
        __syncthreads();
    }
    const float l = s_red[0];

    // ---- V pass: weighted accumulate + copy (streaming store) ----
    const float* vbase  = vc  + ((size_t)bh * TC_ + t0) * D_;
    float*       ovbase = out + VOFF + ((size_t)bh * TK_ + t0) * D_;
    float ax = 0.f, ay = 0.f, az = 0.f, aw = 0.f;
    for (int i = 0; i < CH / 8; i++) {
        int t = i * 8 + w;
        float p = s_sc[t];
        float4 v4 = *(const float4*)(vbase + (size_t)t * D_ + dd);
        __stcs((float4*)(ovbase + (size_t)t * D_ + dd), v4);
        ax += p * v4.x; ay += p * v4.y; az += p * v4.z; aw += p * v4.w;
    }
    s_vacc[w * D_ + dd]     = ax;
    s_vacc[w * D_ + dd + 1] = ay;
    s_vacc[w * D_ + dd + 2] = az;
    s_vacc[w * D_ + dd + 3] = aw;
    __syncthreads();

    if (tid < D_) {
        float s = 0.f;
        #pragma unroll
        for (int g = 0; g < 8; g++) s += s_vacc[g * D_ + tid];
        g_pacc[((size_t)bh * NCH + c) * D_ + tid] = s;
        if (tid == 0) { g_pm[bh * NCH + c] = m; g_pl[bh * NCH + c] = l; }
    }
}

// ---------------- kernel 3: combine partials + new token + write new kv ----------------
// grid 256, block 128. (R5 exact)
__global__ void combine(float* __restrict__ out) {
    __shared__ float s_red[D_];
    const int bh = blockIdx.x;
    const int d  = threadIdx.x;
    const int b  = bh >> 5;
    const int h  = bh & 31;

    const float q  = g_qkv[b * COLS3 +           h * D_ + d];
    const float kn = g_qkv[b * COLS3 + HD_  +    h * D_ + d];
    const float vn = g_qkv[b * COLS3 + 2*HD_ +   h * D_ + d];

    s_red[d] = q * kn;
    __syncthreads();
    for (int off = 64; off > 0; off >>= 1) {
        if (d < off) s_red[d] += s_red[d + off];
        __syncthreads();
    }
    const float snew = s_red[0] * SCALE;

    float M = snew;
    #pragma unroll
    for (int c = 0; c < NCH; c++) M = fmaxf(M, g_pm[bh * NCH + c]);

    float en = __expf(snew - M);
    float L  = en;
    float o  = en * vn;
    #pragma unroll
    for (int c = 0; c < NCH; c++) {
        float wgt = __expf(g_pm[bh * NCH + c] - M);
        L += g_pl[bh * NCH + c] * wgt;
        o += g_pacc[((size_t)bh * NCH + c) * D_ + d] * wgt;
    }
    g_o[b * HD_ + h * D_ + d] = o / L;

    out[KOFF + ((size_t)bh * TK_ + TC_) * D_ + d] = kn;
    out[VOFF + ((size_t)bh * TK_ + TC_) * D_ + d] = vn;
}

// ---------------- kernel 4: output projection o @ Wo, split-K x32 (R5 exact) ----------------
__global__ void out_gemm(const float* __restrict__ Wo) {
    __shared__ float xs[KCH_OUT * 8];
    const int split = blockIdx.y;
    const int col   = blockIdx.x * 256 + threadIdx.x;
    const int k0    = split * KCH_OUT;

    for (int idx = threadIdx.x; idx < KCH_OUT * 8; idx += 256) {
        int kk = idx >> 3, r = idx & 7;
        xs[idx] = g_o[r * HD_ + k0 + kk];
    }
    __syncthreads();

    const float* wp = Wo + (size_t)k0 * DM_ + col;
    float acc[8];
    #pragma unroll
    for (int r = 0; r < 8; r++) acc[r] = 0.f;

    for (int kk = 0; kk < KCH_OUT; kk += 8) {
        float w[8];
        #pragma unroll
        for (int j = 0; j < 8; j++) w[j] = wp[(size_t)(kk + j) * DM_];
        #pragma unroll
        for (int j = 0; j < 8; j++) {
            #pragma unroll
            for (int r = 0; r < 8; r++) acc[r] += xs[(kk + j) * 8 + r] * w[j];
        }
    }
    float* op = g_o_part + (size_t)split * (B_ * DM_) + col;
    #pragma unroll
    for (int r = 0; r < 8; r++) op[(size_t)r * DM_] = acc[r];
}

__global__ void reduce_out(float* __restrict__ out) {
    int i = blockIdx.x * 256 + threadIdx.x;   // < 32768
    float s = 0.f;
    #pragma unroll
    for (int sp = 0; sp < SPLITK_OUT; sp++) s += g_o_part[(size_t)sp * (B_*DM_) + i];
    out[i] = s;
}

// ---------------- launch ----------------
extern "C" void kernel_launch(void* const* d_in, const int* in_sizes, int n_in,
                              void* d_out, int out_size) {
    const float* x       = (const float*)d_in[0];
    const float* Wq      = (const float*)d_in[1];
    const float* Wk      = (const float*)d_in[2];
    const float* Wv      = (const float*)d_in[3];
    const float* Wo      = (const float*)d_in[4];
    const float* k_cache = (const float*)d_in[5];
    const float* v_cache = (const float*)d_in[6];
    float* out = (float*)d_out;

    qkv_gemm<<<dim3(48, SPLITK_QKV), 256>>>(x, Wq, Wk, Wv);
    reduce_qkv<<<(B_ * COLS3) / 256, 256>>>();
    attn_chunk<<<dim3(NCH, NBH), 256>>>(k_cache, v_cache, out);
    combine<<<NBH, D_>>>(out);
    out_gemm<<<dim3(16, SPLITK_OUT), 256>>>(Wo);
    reduce_out<<<(B_ * DM_) / 256, 256>>>(out);
}

// round 11
// speedup vs baseline: 1.0495x; 1.0419x over previous
#include <cuda_runtime.h>
#include <cuda_bf16.h>
#include <cstddef>

// Problem constants
#define B_    8
#define H_    32
#define D_    128
#define DM_   4096
#define TC_   8192
#define TK_   8193
#define HD_   4096          // H*D
#define COLS3 12288         // 3*HD
#define SPLITK_QKV 32
#define KCH_QKV    128      // DM/SPLITK_QKV
#define SPLITK_OUT 32
#define KCH_OUT    128      // HD/SPLITK_OUT
#define CH    256           // keys per attention chunk (single change vs R5)
#define NCH   32            // TC/CH
#define NBH   256           // B*H
#define SCALE 0.08838834764831845f   // 1/sqrt(128)

#define OUT_SZ   (B_*DM_)                           // 32768
#define KCAT_SZ  ((size_t)NBH*TK_*D_)               // 268468224
#define KOFF     ((size_t)OUT_SZ)
#define VOFF     ((size_t)OUT_SZ + KCAT_SZ)

// ---------------- scratch (device globals; no allocation) ----------------
__device__ float g_qkv_part[SPLITK_QKV * B_ * COLS3];  // 12.6 MB
__device__ float g_qkv[B_ * COLS3];
__device__ float g_pm[NBH * NCH];
__device__ float g_pl[NBH * NCH];
__device__ float g_pacc[(size_t)NBH * NCH * D_];       // 4 MB
__device__ float g_o[B_ * HD_];
__device__ float g_o_part[SPLITK_OUT * B_ * HD_];      // 4 MB

// ---------------- kernel 1: QKV projection, split-K x32 (R5 exact) ----------------
// grid (48, 32), block 256.
__global__ void qkv_gemm(const float* __restrict__ x,
                         const float* __restrict__ Wq,
                         const float* __restrict__ Wk,
                         const float* __restrict__ Wv) {
    __shared__ float xs[KCH_QKV * 8];   // xs[kk*8 + r]
    const int split = blockIdx.y;
    const int col   = blockIdx.x * 256 + threadIdx.x;
    const int k0    = split * KCH_QKV;

    for (int idx = threadIdx.x; idx < KCH_QKV * 8; idx += 256) {
        int kk = idx >> 3, r = idx & 7;
        xs[idx] = x[r * DM_ + k0 + kk];
    }
    __syncthreads();

    const int mat  = col >> 12;           // 0:q 1:k 2:v
    const int lcol = col & 4095;
    const float* W = (mat == 0) ? Wq : ((mat == 1) ? Wk : Wv);
    const float* wp = W + (size_t)k0 * HD_ + lcol;

    float acc[8];
    #pragma unroll
    for (int r = 0; r < 8; r++) acc[r] = 0.f;

    for (int kk = 0; kk < KCH_QKV; kk += 8) {
        float w[8];
        #pragma unroll
        for (int j = 0; j < 8; j++) w[j] = wp[(size_t)(kk + j) * HD_];
        #pragma unroll
        for (int j = 0; j < 8; j++) {
            #pragma unroll
            for (int r = 0; r < 8; r++) acc[r] += xs[(kk + j) * 8 + r] * w[j];
        }
    }
    float* op = g_qkv_part + (size_t)split * (B_ * COLS3) + col;
    #pragma unroll
    for (int r = 0; r < 8; r++) op[(size_t)r * COLS3] = acc[r];
}

__global__ void reduce_qkv() {
    int i = blockIdx.x * 256 + threadIdx.x;   // < 98304
    float s = 0.f;
    #pragma unroll
    for (int sp = 0; sp < SPLITK_QKV; sp++) s += g_qkv_part[(size_t)sp * (B_*COLS3) + i];
    g_qkv[i] = s;
}

// ---------------- kernel 2: fused cache-copy + flash attention chunk ----------------
// grid (NCH, NBH), block 256. R5 body with CH=256 (one score per thread).
__global__ void attn_chunk(const float* __restrict__ kc,
                           const float* __restrict__ vc,
                           float* __restrict__ out) {
    __shared__ float s_q[D_];
    __shared__ float s_sc[CH];
    __shared__ float s_red[256];
    __shared__ float s_vacc[8 * D_];

    const int bh  = blockIdx.y;
    const int c   = blockIdx.x;
    const int tid = threadIdx.x;
    const int b   = bh >> 5;
    const int h   = bh & 31;

    if (tid < D_) s_q[tid] = g_qkv[b * COLS3 + h * D_ + tid];
    __syncthreads();

    const int t0   = c * CH;
    const int w    = tid >> 5;
    const int lane = tid & 31;
    const int dd   = lane * 4;

    const float qx = s_q[dd], qy = s_q[dd+1], qz = s_q[dd+2], qw = s_q[dd+3];

    // ---- K pass: dot + copy ----
    const float* kbase  = kc  + ((size_t)bh * TC_ + t0) * D_;
    float*       okbase = out + KOFF + ((size_t)bh * TK_ + t0) * D_;
    for (int i = 0; i < CH / 8; i++) {
        int t = w * (CH / 8) + i;
        float4 k4 = *(const float4*)(kbase + (size_t)t * D_ + dd);
        *(float4*)(okbase + (size_t)t * D_ + dd) = k4;
        float d = k4.x*qx + k4.y*qy + k4.z*qz + k4.w*qw;
        d += __shfl_down_sync(0xffffffffu, d, 16);
        d += __shfl_down_sync(0xffffffffu, d, 8);
        d += __shfl_down_sync(0xffffffffu, d, 4);
        d += __shfl_down_sync(0xffffffffu, d, 2);
        d += __shfl_down_sync(0xffffffffu, d, 1);
        if (lane == 0) s_sc[t] = d * SCALE;
    }
    __syncthreads();

    // ---- local max (256 scores, one per thread) ----
    s_red[tid] = s_sc[tid];
    __syncthreads();
    for (int off = 128; off > 0; off >>= 1) {
        if (tid < off) s_red[tid] = fmaxf(s_red[tid], s_red[tid + off]);
        __syncthreads();
    }
    const float m = s_red[0];
    __syncthreads();

    // ---- exp + sum ----
    float e0 = __expf(s_sc[tid] - m);
    s_sc[tid] = e0;
    s_red[tid] = e0;
    __syncthreads();
    for (int off = 128; off > 0; off >>= 1) {
        if (tid < off) s_red[tid] += s_red[tid + off];
        __syncthreads();
    }
    const float l = s_red[0];

    // ---- V pass: weighted accumulate + copy ----
    const float* vbase  = vc  + ((size_t)bh * TC_ + t0) * D_;
    float*       ovbase = out + VOFF + ((size_t)bh * TK_ + t0) * D_;
    float ax = 0.f, ay = 0.f, az = 0.f, aw = 0.f;
    for (int i = 0; i < CH / 8; i++) {
        int t = i * 8 + w;
        float p = s_sc[t];
        float4 v4 = *(const float4*)(vbase + (size_t)t * D_ + dd);
        *(float4*)(ovbase + (size_t)t * D_ + dd) = v4;
        ax += p * v4.x; ay += p * v4.y; az += p * v4.z; aw += p * v4.w;
    }
    s_vacc[w * D_ + dd]     = ax;
    s_vacc[w * D_ + dd + 1] = ay;
    s_vacc[w * D_ + dd + 2] = az;
    s_vacc[w * D_ + dd + 3] = aw;
    __syncthreads();

    if (tid < D_) {
        float s = 0.f;
        #pragma unroll
        for (int g = 0; g < 8; g++) s += s_vacc[g * D_ + tid];
        g_pacc[((size_t)bh * NCH + c) * D_ + tid] = s;
        if (tid == 0) { g_pm[bh * NCH + c] = m; g_pl[bh * NCH + c] = l; }
    }
}

// ---------------- kernel 3: combine partials + new token + write new kv ----------------
// grid 256, block 128. (R5 body; NCH now 32)
__global__ void combine(float* __restrict__ out) {
    __shared__ float s_red[D_];
    const int bh = blockIdx.x;
    const int d  = threadIdx.x;
    const int b  = bh >> 5;
    const int h  = bh & 31;

    const float q  = g_qkv[b * COLS3 +           h * D_ + d];
    const float kn = g_qkv[b * COLS3 + HD_  +    h * D_ + d];
    const float vn = g_qkv[b * COLS3 + 2*HD_ +   h * D_ + d];

    s_red[d] = q * kn;
    __syncthreads();
    for (int off = 64; off > 0; off >>= 1) {
        if (d < off) s_red[d] += s_red[d + off];
        __syncthreads();
    }
    const float snew = s_red[0] * SCALE;

    float M = snew;
    #pragma unroll
    for (int c = 0; c < NCH; c++) M = fmaxf(M, g_pm[bh * NCH + c]);

    float en = __expf(snew - M);
    float L  = en;
    float o  = en * vn;
    #pragma unroll
    for (int c = 0; c < NCH; c++) {
        float wgt = __expf(g_pm[bh * NCH + c] - M);
        L += g_pl[bh * NCH + c] * wgt;
        o += g_pacc[((size_t)bh * NCH + c) * D_ + d] * wgt;
    }
    g_o[b * HD_ + h * D_ + d] = o / L;

    out[KOFF + ((size_t)bh * TK_ + TC_) * D_ + d] = kn;
    out[VOFF + ((size_t)bh * TK_ + TC_) * D_ + d] = vn;
}

// ---------------- kernel 4: output projection o @ Wo, split-K x32 (R5 exact) ----------------
__global__ void out_gemm(const float* __restrict__ Wo) {
    __shared__ float xs[KCH_OUT * 8];
    const int split = blockIdx.y;
    const int col   = blockIdx.x * 256 + threadIdx.x;
    const int k0    = split * KCH_OUT;

    for (int idx = threadIdx.x; idx < KCH_OUT * 8; idx += 256) {
        int kk = idx >> 3, r = idx & 7;
        xs[idx] = g_o[r * HD_ + k0 + kk];
    }
    __syncthreads();

    const float* wp = Wo + (size_t)k0 * DM_ + col;
    float acc[8];
    #pragma unroll
    for (int r = 0; r < 8; r++) acc[r] = 0.f;

    for (int kk = 0; kk < KCH_OUT; kk += 8) {
        float w[8];
        #pragma unroll
        for (int j = 0; j < 8; j++) w[j] = wp[(size_t)(kk + j) * DM_];
        #pragma unroll
        for (int j = 0; j < 8; j++) {
            #pragma unroll
            for (int r = 0; r < 8; r++) acc[r] += xs[(kk + j) * 8 + r] * w[j];
        }
    }
    float* op = g_o_part + (size_t)split * (B_ * DM_) + col;
    #pragma unroll
    for (int r = 0; r < 8; r++) op[(size_t)r * DM_] = acc[r];
}

__global__ void reduce_out(float* __restrict__ out) {
    int i = blockIdx.x * 256 + threadIdx.x;   // < 32768
    float s = 0.f;
    #pragma unroll
    for (int sp = 0; sp < SPLITK_OUT; sp++) s += g_o_part[(size_t)sp * (B_*DM_) + i];
    out[i] = s;
}

// ---------------- launch ----------------
extern "C" void kernel_launch(void* const* d_in, const int* in_sizes, int n_in,
                              void* d_out, int out_size) {
    const float* x       = (const float*)d_in[0];
    const float* Wq      = (const float*)d_in[1];
    const float* Wk      = (const float*)d_in[2];
    const float* Wv      = (const float*)d_in[3];
    const float* Wo      = (const float*)d_in[4];
    const float* k_cache = (const float*)d_in[5];
    const float* v_cache = (const float*)d_in[6];
    float* out = (float*)d_out;

    qkv_gemm<<<dim3(48, SPLITK_QKV), 256>>>(x, Wq, Wk, Wv);
    reduce_qkv<<<(B_ * COLS3) / 256, 256>>>();
    attn_chunk<<<dim3(NCH, NBH), 256>>>(k_cache, v_cache, out);
    combine<<<NBH, D_>>>(out);
    out_gemm<<<dim3(16, SPLITK_OUT), 256>>>(Wo);
    reduce_out<<<(B_ * DM_) / 256, 256>>>(out);
}